// round 3
// baseline (speedup 1.0000x reference)
#include <cuda_runtime.h>
#include <cstdint>

// Problem constants
#define TT   2048
#define HH   512
#define NB   32
#define II   88
#define TH   (TT*HH)          // 1048576 (per-batch stride in hiddens)
#define NTOT (NB*TH)          // 33554432 (one hiddens tensor)
#define NT   (NB*TT)          // 65536 rows in xproj GEMM
#define NCTA 128
#define NGRP 8                // batch groups (independent barrier domains)
#define GCTA 16               // CTAs per group

// Device scratch (static allocations are the sanctioned workaround)
__device__ float    g_xp[NT * HH];      // xproj laid out [t][n][h], 128 MB
__device__ unsigned g_barg[NGRP * 32];  // per-group barrier counters, 128B apart

// ---------------------------------------------------------------------------
// Packed f32x2 helpers
// ---------------------------------------------------------------------------
__device__ __forceinline__ unsigned long long pack_f32x2(float lo, float hi) {
    unsigned long long r;
    asm("mov.b64 %0, {%1, %2};" : "=l"(r) : "f"(lo), "f"(hi));
    return r;
}
__device__ __forceinline__ void unpack_f32x2(unsigned long long v, float& lo, float& hi) {
    asm("mov.b64 {%0, %1}, %2;" : "=f"(lo), "=f"(hi) : "l"(v));
}
__device__ __forceinline__ void fma2(unsigned long long& acc,
                                     unsigned long long a, unsigned long long b) {
    asm("fma.rn.f32x2 %0, %1, %2, %0;" : "+l"(acc) : "l"(a), "l"(b));
}

// ---------------------------------------------------------------------------
// Phase 1: xproj[t][n][h] = sum_i x[n][t][i] * W_ih[h][i] + b_ih[h]
// Block: 512 threads (one per h). Each block handles 32 consecutive (n,t) rows
// (same n, consecutive t). W_ih row in registers, x rows staged in smem,
// consumed via float4 LDS (4x fewer shared loads than scalar).
// ---------------------------------------------------------------------------
__global__ void __launch_bounds__(512, 1) xproj_kernel(
    const float* __restrict__ x,
    const float* __restrict__ W_ih,
    const float* __restrict__ b_ih)
{
    __shared__ __align__(16) float xs[32][II];
    const int h   = threadIdx.x;          // 0..511
    const int nt0 = blockIdx.x * 32;
    const int n   = nt0 / TT;             // same n for the whole block
    const int t0  = nt0 % TT;

    float w[II];
#pragma unroll
    for (int i = 0; i < II; i++) w[i] = W_ih[h * II + i];
    const float b = b_ih[h];

    for (int f = threadIdx.x; f < 32 * II; f += 512) {
        xs[f / II][f % II] = x[nt0 * II + f];
    }
    __syncthreads();

#pragma unroll 1
    for (int j = 0; j < 32; j++) {
        float s = b;
        const float4* xr = reinterpret_cast<const float4*>(&xs[j][0]);
#pragma unroll
        for (int i4 = 0; i4 < II / 4; i4++) {
            float4 xv = xr[i4];
            s += w[4 * i4 + 0] * xv.x;
            s += w[4 * i4 + 1] * xv.y;
            s += w[4 * i4 + 2] * xv.z;
            s += w[4 * i4 + 3] * xv.w;
        }
        g_xp[((t0 + j) * NB + n) * HH + h] = s;
    }
}

// ---------------------------------------------------------------------------
// Phase 2: h0 = initial + xproj[0]; also resets the per-group barriers.
// ---------------------------------------------------------------------------
__global__ void h0_kernel(const float* __restrict__ initial,
                          float* __restrict__ out, int dup)
{
    const int n = blockIdx.x;     // 0..31
    const int h = threadIdx.x;    // 0..511
    float v = initial[n * HH + h] + g_xp[(0 * NB + n) * HH + h];
    out[n * TH + 0 * HH + h] = v;
    if (dup) out[NTOT + n * TH + h] = v;
    if (blockIdx.x == 0 && threadIdx.x < NGRP) g_barg[threadIdx.x * 32] = 0u;
}

// ---------------------------------------------------------------------------
// Warp butterfly: reduce 32 per-lane partials across 32 lanes so that
// lane L ends up owning the full sum of original index L.
// ---------------------------------------------------------------------------
template <int OFF, int M>
__device__ __forceinline__ void red_round(float* acc, int lane)
{
    const bool up = (lane & OFF) != 0;
#pragma unroll
    for (int i = 0; i < M; i++) {
        float keep = up ? acc[i + M] : acc[i];
        float send = up ? acc[i]     : acc[i + M];
        float recv = __shfl_xor_sync(0xffffffffu, send, OFF);
        acc[i] = keep + recv;
    }
}

// ---------------------------------------------------------------------------
// Phase 3: persistent recurrence kernel.
// Grid: 128 CTAs = 16 row-groups (32 h-rows) x 8 batch-groups (4 batches).
// CTA: 256 threads = 4 row-subgroups (8 rows) x 64 k-chunks.
// Thread: rows r0..r0+7, batches n0..n0+3, k-pairs {2*kc + 128*jp, jp=0..3}.
// W_hh slice pinned in packed-f32x2 registers for all 2047 steps.
// Barrier domain: the 16 CTAs sharing a batch group (true dependency set).
// ---------------------------------------------------------------------------
__global__ void __launch_bounds__(256, 1) rnn_kernel(
    const float* __restrict__ W_hh,
    float* __restrict__ out, int dup)
{
    __shared__ __align__(16) float h_s[4 * HH];  // h_{t-1} for 4 batches
    __shared__ float red[4][32];                 // cross-warp partial combine

    const int tid  = threadIdx.x;
    const int kc   = tid & 63;       // k-chunk id (pairs at 2*kc + 128*jp)
    const int rsub = tid >> 6;       // 0..3
    const int bg   = blockIdx.x & 7; // batch group
    const int rg   = blockIdx.x >> 3;// row group
    const int n0   = bg * 4;
    const int r0   = rg * 32 + rsub * 8;
    const int lane = tid & 31;

    volatile unsigned* bar = (volatile unsigned*)&g_barg[bg * 32];

    // Register-resident packed W_hh slice:
    // w2[r][jp] = (W[(r0+r)*512 + 2*kc+128*jp], W[(r0+r)*512 + 2*kc+128*jp+1])
    unsigned long long w2[8][4];
#pragma unroll
    for (int r = 0; r < 8; r++)
#pragma unroll
        for (int jp = 0; jp < 4; jp++) {
            const float* p = &W_hh[(r0 + r) * HH + 2 * kc + 128 * jp];
            w2[r][jp] = pack_f32x2(p[0], p[1]);
        }

    const bool writer = (kc < 32);           // warp0 of each rsub owns outputs
    const int  rl = lane >> 2;               // output row-local  (0..7)
    const int  nl = lane & 3;                // output batch-local(0..3)
    const int  outRow = r0 + rl;             // global h index of my output
    const int  outN   = n0 + nl;             // global batch of my output

    // fill-phase mapping: thread loads 8 consecutive h-floats of one batch
    const int ff  = tid * 8;                 // 0..2040
    const int fn  = ff >> 9;                 // batch-local 0..3
    const int fk  = ff & 511;                // k offset (multiple of 8)

    for (int t = 1; t < TT; t++) {
        // ---- stage h_{t-1} (globally visible in L2 via per-group barrier)
        {
            const float4* src = reinterpret_cast<const float4*>(
                out + (n0 + fn) * TH + (t - 1) * HH + fk);
            float4 a = __ldcg(src);
            float4 c = __ldcg(src + 1);
            *reinterpret_cast<float4*>(&h_s[fn * HH + fk])     = a;
            *reinterpret_cast<float4*>(&h_s[fn * HH + fk + 4]) = c;
        }
        // ---- prefetch my xproj value (independent of h; contiguous t-slice)
        float xpv = 0.0f;
        if (writer)
            xpv = __ldg(&g_xp[((t - 1) * NB + outN) * HH + outRow]);
        __syncthreads();

        // ---- main loop: 128 FFMA2 (= 256 MACs), 16 LDS.64, conflict-free
        unsigned long long acc2[32];
#pragma unroll
        for (int i = 0; i < 32; i++) acc2[i] = 0ull;
#pragma unroll
        for (int jp = 0; jp < 4; jp++) {
            const int k = 2 * kc + 128 * jp;
            unsigned long long hp0 = *reinterpret_cast<const unsigned long long*>(&h_s[0 * HH + k]);
            unsigned long long hp1 = *reinterpret_cast<const unsigned long long*>(&h_s[1 * HH + k]);
            unsigned long long hp2 = *reinterpret_cast<const unsigned long long*>(&h_s[2 * HH + k]);
            unsigned long long hp3 = *reinterpret_cast<const unsigned long long*>(&h_s[3 * HH + k]);
#pragma unroll
            for (int r = 0; r < 8; r++) {
                fma2(acc2[r * 4 + 0], w2[r][jp], hp0);
                fma2(acc2[r * 4 + 1], w2[r][jp], hp1);
                fma2(acc2[r * 4 + 2], w2[r][jp], hp2);
                fma2(acc2[r * 4 + 3], w2[r][jp], hp3);
            }
        }

        // ---- unpack (even-k + odd-k halves) then warp butterfly
        float acc[32];
#pragma unroll
        for (int i = 0; i < 32; i++) {
            float lo, hi;
            unpack_f32x2(acc2[i], lo, hi);
            acc[i] = lo + hi;
        }
        red_round<16, 16>(acc, lane);
        red_round< 8,  8>(acc, lane);
        red_round< 4,  4>(acc, lane);
        red_round< 2,  2>(acc, lane);
        red_round< 1,  1>(acc, lane);

        // ---- cross-warp combine (kc>=32 half contributes via smem)
        if (!writer) red[rsub][lane] = acc[0];
        __syncthreads();

        if (writer) {
            const float v = acc[0] + red[rsub][lane] + xpv;
            const int oi = outN * TH + t * HH + outRow;
            out[oi] = v;
            if (dup) out[NTOT + oi] = v;
        }
        __syncthreads();   // all writers' STG issued before tid0's fence

        // ---- per-group barrier: one cumulative fence + arrive by tid0
        if (tid == 0) {
            __threadfence();                 // release all CTA stores (HB via bar)
            atomicAdd((unsigned*)&g_barg[bg * 32], 1u);
            const unsigned target = (unsigned)t * GCTA;
            while (*bar < target) { }
            __threadfence();                 // acquire before next-step reads
        }
        __syncthreads();
    }
}

// ---------------------------------------------------------------------------
// Launch: inputs in metadata order: x, initial, W_ih, b_ih, W_hh
// ---------------------------------------------------------------------------
extern "C" void kernel_launch(void* const* d_in, const int* in_sizes, int n_in,
                              void* d_out, int out_size)
{
    const float* x       = (const float*)d_in[0];
    const float* initial = (const float*)d_in[1];
    const float* W_ih    = (const float*)d_in[2];
    const float* b_ih    = (const float*)d_in[3];
    const float* W_hh    = (const float*)d_in[4];
    float* out = (float*)d_out;
    const int dup = (out_size >= 2 * NTOT) ? 1 : 0;

    xproj_kernel<<<NT / 32, 512>>>(x, W_ih, b_ih);
    h0_kernel<<<NB, HH>>>(initial, out, dup);
    rnn_kernel<<<NCTA, 256>>>(W_hh, out, dup);
}

// round 4
// speedup vs baseline: 1.4289x; 1.4289x over previous
#include <cuda_runtime.h>
#include <cstdint>

// Problem constants
#define TT   2048
#define HH   512
#define NB   32
#define II   88
#define TH   (TT*HH)           // per-batch stride in hiddens
#define NTOT (NB*TH)           // one hiddens tensor (33554432)
#define NROWS (NB*TT)          // 65536 (n,t) rows
#define NCTA 128
#define NGRP 8                 // groups of 16 CTAs; group = 4 batches x 2 chains
#define GCTA 16

// Device scratch
__device__ float    g_p0[NROWS * HH];   // p0[t][n][h] = W_ih x_t + b        (=xproj)
__device__ float    g_p1[NROWS * HH];   // p1[t][n][h] = (W W_ih) x_t + W b  (=W xproj)
__device__ float    g_W2[HH * HH];      // W_hh^2
__device__ float    g_WT[HH * HH];      // W_hh transposed (for prologue)
__device__ float    g_Wp1[HH * II];     // W_hh * W_ih
__device__ float    g_b1[HH];           // W_hh * b_ih
__device__ unsigned g_flag[NCTA * 32];  // per-CTA step flags, 128B apart

// ---------------- release/acquire helpers ----------------
__device__ __forceinline__ void st_release_gpu(unsigned* p, unsigned v) {
    asm volatile("st.release.gpu.global.u32 [%0], %1;" :: "l"(p), "r"(v) : "memory");
}
__device__ __forceinline__ unsigned ld_acquire_gpu(const unsigned* p) {
    unsigned v;
    asm volatile("ld.acquire.gpu.global.u32 %0, [%1];" : "=r"(v) : "l"(p) : "memory");
    return v;
}

// ---------------------------------------------------------------------------
// W transpose: g_WT[k][r] = W[r][k]   (for coalesced prologue matvec)
// ---------------------------------------------------------------------------
__global__ void transp_kernel(const float* __restrict__ W) {
    __shared__ float tile[32][33];
    int rx = blockIdx.x * 32, ry = blockIdx.y * 32;
    tile[threadIdx.y][threadIdx.x] = W[(ry + threadIdx.y) * HH + rx + threadIdx.x];
    __syncthreads();
    g_WT[(rx + threadIdx.y) * HH + ry + threadIdx.x] = tile[threadIdx.x][threadIdx.y];
}

// ---------------------------------------------------------------------------
// W2 = W * W : block handles 8 rows; thread = one output column.
// ---------------------------------------------------------------------------
__global__ void __launch_bounds__(512, 1) mm512_kernel(const float* __restrict__ W) {
    __shared__ float as[8][HH];
    const int r0 = blockIdx.x * 8;
    for (int f = threadIdx.x; f < 8 * HH; f += 512)
        as[f >> 9][f & 511] = W[r0 * HH + f];
    __syncthreads();
    const int c = threadIdx.x;
    float acc[8];
#pragma unroll
    for (int r = 0; r < 8; r++) acc[r] = 0.0f;
#pragma unroll 4
    for (int k = 0; k < HH; k++) {
        const float bv = W[k * HH + c];
#pragma unroll
        for (int r = 0; r < 8; r++) acc[r] += as[r][k] * bv;
    }
#pragma unroll
    for (int r = 0; r < 8; r++) g_W2[(r0 + r) * HH + c] = acc[r];
}

// ---------------------------------------------------------------------------
// Wp1 = W * W_ih (512x88), b1 = W * b_ih. Block = one row r, 96 threads.
// ---------------------------------------------------------------------------
__global__ void projw_kernel(const float* __restrict__ W,
                             const float* __restrict__ W_ih,
                             const float* __restrict__ b_ih) {
    __shared__ float ar[HH];
    const int r = blockIdx.x;
    for (int f = threadIdx.x; f < HH; f += 96) ar[f] = W[r * HH + f];
    __syncthreads();
    const int i = threadIdx.x;
    if (i < II) {
        float acc = 0.0f;
#pragma unroll 4
        for (int k = 0; k < HH; k++) acc += ar[k] * W_ih[k * II + i];
        g_Wp1[r * II + i] = acc;
    } else if (i == II) {
        float acc = 0.0f;
#pragma unroll 4
        for (int k = 0; k < HH; k++) acc += ar[k] * b_ih[k];
        g_b1[r] = acc;
    }
}

// ---------------------------------------------------------------------------
// Dual projection: p0[t][n][h] = W_ih x + b ; p1[t][n][h] = Wp1 x + b1.
// Block stages 64 x-rows once, runs two weight sweeps.
// ---------------------------------------------------------------------------
__global__ void __launch_bounds__(512, 1) proj2_kernel(
    const float* __restrict__ x,
    const float* __restrict__ W_ih,
    const float* __restrict__ b_ih)
{
    __shared__ __align__(16) float xs[64][II];
    const int h   = threadIdx.x;
    const int rr0 = blockIdx.x * 64;           // 64 | 2048 -> one n per block

    for (int f = threadIdx.x; f < 64 * II; f += 512)
        xs[f / II][f % II] = x[rr0 * II + f];
    __syncthreads();

    const int n  = rr0 >> 11;                  // rr = n*2048 + t
    const int t0 = rr0 & 2047;

    // sweep 0: (W_ih, b) -> p0
    {
        float w[II];
#pragma unroll
        for (int i = 0; i < II; i++) w[i] = W_ih[h * II + i];
        const float b = b_ih[h];
#pragma unroll 1
        for (int j = 0; j < 64; j++) {
            float s = b;
            const float4* xr = reinterpret_cast<const float4*>(&xs[j][0]);
#pragma unroll
            for (int i4 = 0; i4 < II / 4; i4++) {
                float4 xv = xr[i4];
                s += w[4*i4+0]*xv.x; s += w[4*i4+1]*xv.y;
                s += w[4*i4+2]*xv.z; s += w[4*i4+3]*xv.w;
            }
            g_p0[((t0 + j) * NB + n) * HH + h] = s;
        }
    }
    // sweep 1: (Wp1, b1) -> p1
    {
        float w[II];
#pragma unroll
        for (int i = 0; i < II; i++) w[i] = g_Wp1[h * II + i];
        const float b = g_b1[h];
#pragma unroll 1
        for (int j = 0; j < 64; j++) {
            float s = b;
            const float4* xr = reinterpret_cast<const float4*>(&xs[j][0]);
#pragma unroll
            for (int i4 = 0; i4 < II / 4; i4++) {
                float4 xv = xr[i4];
                s += w[4*i4+0]*xv.x; s += w[4*i4+1]*xv.y;
                s += w[4*i4+2]*xv.z; s += w[4*i4+3]*xv.w;
            }
            g_p1[((t0 + j) * NB + n) * HH + h] = s;
        }
    }
}

// ---------------------------------------------------------------------------
// h0 = initial + p0[0]; resets step flags.
// ---------------------------------------------------------------------------
__global__ void h0_kernel(const float* __restrict__ initial,
                          float* __restrict__ out, int dup)
{
    const int n = blockIdx.x, h = threadIdx.x;
    float v = initial[n * HH + h] + g_p0[(0 * NB + n) * HH + h];
    out[n * TH + h] = v;
    if (dup) out[NTOT + n * TH + h] = v;
    if (blockIdx.x == 0 && threadIdx.x < NCTA) g_flag[threadIdx.x * 32] = 0u;
}

// ---------------------------------------------------------------------------
// Prologue: h_1 = W h_0 + p0[0]. Grid 32 (n), 512 threads (row).
// ---------------------------------------------------------------------------
__global__ void __launch_bounds__(512, 1) prologue_kernel(
    float* __restrict__ out, int dup)
{
    __shared__ float hs[HH];
    const int n = blockIdx.x, r = threadIdx.x;
    hs[r] = out[n * TH + r];          // h_0
    __syncthreads();
    float acc = g_p0[(0 * NB + n) * HH + r];
#pragma unroll 8
    for (int k = 0; k < HH; k++) acc += g_WT[k * HH + r] * hs[k];
    out[n * TH + HH + r] = acc;       // t = 1
    if (dup) out[NTOT + n * TH + HH + r] = acc;
}

// ---------------------------------------------------------------------------
// Warp butterfly: lane L ends owning the full sum of original index L.
// ---------------------------------------------------------------------------
template <int OFF, int M>
__device__ __forceinline__ void red_round(float* acc, int lane)
{
    const bool up = (lane & OFF) != 0;
#pragma unroll
    for (int i = 0; i < M; i++) {
        float keep = up ? acc[i + M] : acc[i];
        float send = up ? acc[i]     : acc[i + M];
        float recv = __shfl_xor_sync(0xffffffffu, send, OFF);
        acc[i] = keep + recv;
    }
}

// ---------------------------------------------------------------------------
// Persistent recurrence, D=2 chains: h_t = W2 h_{t-2} + p1[t-2] + p0[t-1].
// 128 CTAs = 8 groups x 16 CTAs. Group = 8 streams (4 batches x 2 chains).
// CTA = 32 rows x 8 streams. Warp = 4 rows x 8 streams x full k (no cross-
// warp reduce). 1023 barrier steps, flag-array release/acquire barrier.
// ---------------------------------------------------------------------------
__global__ void __launch_bounds__(256, 1) rnn_kernel(
    float* __restrict__ out, int dup)
{
    __shared__ __align__(16) float h_s[8 * HH];   // 16 KB: 8 streams' h_{t-2}

    const int tid  = threadIdx.x;
    const int wid  = tid >> 5;
    const int lane = tid & 31;
    const int bg   = blockIdx.x >> 4;    // group 0..7
    const int rg   = blockIdx.x & 15;    // CTA within group
    const int n0   = bg * 4;

    // Register W2 slice: warp owns rows rowbase..rowbase+3, lane owns k = lane+32j
    const int rowbase = rg * 32 + wid * 4;
    float w[4][16];
#pragma unroll
    for (int r = 0; r < 4; r++)
#pragma unroll
        for (int j = 0; j < 16; j++)
            w[r][j] = g_W2[(rowbase + r) * HH + lane + 32 * j];

    // My output after butterfly: acc index L = r*8 + s
    const int myRow = rowbase + (lane >> 3);
    const int ms    = lane & 7;
    const int myN   = n0 + (ms >> 1);
    const int myC   = ms & 1;

    // Staging map: 32 threads per stream; thread covers k = si*4 + m*128
    const int ss = tid >> 5;            // stream 0..7
    const int si = tid & 31;
    const int sN = n0 + (ss >> 1);
    const int sC = ss & 1;

    unsigned* myFlag = &g_flag[(bg * GCTA + rg) * 32];
    const unsigned* pollFlag = &g_flag[(bg * GCTA + (tid & 15)) * 32];

    for (int k = 1; k <= (TT - 2) / 2; k++) {
        // ---- stage h_{t-2} for my stream slice (coalesced float4)
        {
            const int tprev = sC + 2 * (k - 1);
            const float4* src = reinterpret_cast<const float4*>(
                out + (size_t)sN * TH + (size_t)tprev * HH);
            float4* dst = reinterpret_cast<float4*>(&h_s[ss * HH]);
#pragma unroll
            for (int m = 0; m < 4; m++)
                dst[si + m * 32] = __ldcg(src + si + m * 32);
        }
        // ---- prefetch my u = p1[t-2] + p0[t-1] (independent of h)
        const int tout = myC + 2 * k;
        const float uv =
            __ldg(&g_p1[((tout - 2) * NB + myN) * HH + myRow]) +
            __ldg(&g_p0[((tout - 1) * NB + myN) * HH + myRow]);
        __syncthreads();

        // ---- 512 FMA per thread: 4 rows x 8 streams x 16 k-values
        float acc[32];
#pragma unroll
        for (int i = 0; i < 32; i++) acc[i] = 0.0f;
#pragma unroll
        for (int j = 0; j < 16; j++) {
            const int kq = lane + 32 * j;
            float hv[8];
#pragma unroll
            for (int s = 0; s < 8; s++) hv[s] = h_s[s * HH + kq];
#pragma unroll
            for (int r = 0; r < 4; r++)
#pragma unroll
                for (int s = 0; s < 8; s++)
                    acc[r * 8 + s] += w[r][j] * hv[s];
        }

        // ---- butterfly: lane L owns acc index L = (row r = L>>3, stream s = L&7)
        red_round<16, 16>(acc, lane);
        red_round< 8,  8>(acc, lane);
        red_round< 4,  4>(acc, lane);
        red_round< 2,  2>(acc, lane);
        red_round< 1,  1>(acc, lane);

        const float v = acc[0] + uv;
        const size_t oi = (size_t)myN * TH + (size_t)tout * HH + myRow;
        out[oi] = v;
        if (dup) out[NTOT + oi] = v;
        __syncthreads();                      // all CTA stores issued

        // ---- group barrier: per-CTA release flag, 16 parallel acquire polls
        if (tid == 0) st_release_gpu(myFlag, (unsigned)k);
        if (tid < GCTA) {
            while (ld_acquire_gpu(pollFlag) < (unsigned)k) { }
        }
        __syncthreads();
    }
}

// ---------------------------------------------------------------------------
// Launch: inputs in metadata order: x, initial, W_ih, b_ih, W_hh
// ---------------------------------------------------------------------------
extern "C" void kernel_launch(void* const* d_in, const int* in_sizes, int n_in,
                              void* d_out, int out_size)
{
    const float* x       = (const float*)d_in[0];
    const float* initial = (const float*)d_in[1];
    const float* W_ih    = (const float*)d_in[2];
    const float* b_ih    = (const float*)d_in[3];
    const float* W_hh    = (const float*)d_in[4];
    float* out = (float*)d_out;
    const int dup = (out_size >= 2 * NTOT) ? 1 : 0;

    dim3 tb(32, 32);
    dim3 tg(16, 16);
    transp_kernel<<<tg, tb>>>(W_hh);
    mm512_kernel<<<HH / 8, 512>>>(W_hh);
    projw_kernel<<<HH, 96>>>(W_hh, W_ih, b_ih);
    proj2_kernel<<<NROWS / 64, 512>>>(x, W_ih, b_ih);
    h0_kernel<<<NB, HH>>>(initial, out, dup);
    prologue_kernel<<<NB, HH>>>(out, dup);
    rnn_kernel<<<NCTA, 256>>>(out, dup);
}

// round 5
// speedup vs baseline: 1.5568x; 1.0895x over previous
#include <cuda_runtime.h>
#include <cstdint>

// Problem constants
#define TT   2048
#define HH   512
#define NB   32
#define II   88
#define TH   (TT*HH)           // per-batch stride in hiddens
#define NTOT (NB*TH)           // one hiddens tensor (33554432)
#define NROWS (NB*TT)          // 65536 (n,t) rows
#define NCTA 128
#define GCTA 16                // CTAs per barrier group
#define KSTEPS 511             // D=4: (2048-4)/4 = 511 steps

// Device scratch
__device__ float    g_p0[NROWS * HH];   // p0[t][n][h] = W_ih x_t + b
__device__ float    g_p1[NROWS * HH];   // p1[t][n][h] = (W W_ih) x_t + W b
__device__ float    g_p2[NROWS * HH];   // p2 = W^2 ...
__device__ float    g_p3[NROWS * HH];   // p3 = W^3 ...
__device__ float    g_W2[HH * HH];      // W^2
__device__ float    g_W4[HH * HH];      // W^4
__device__ float    g_WT[HH * HH];      // W transposed (prologue)
__device__ float    g_Wp1[HH * II];     // W   * W_ih
__device__ float    g_Wp2[HH * II];     // W^2 * W_ih
__device__ float    g_Wp3[HH * II];     // W^3 * W_ih
__device__ float    g_b1[HH], g_b2[HH], g_b3[HH];
__device__ unsigned g_flag[NCTA * 32];  // per-CTA step flags, 128B apart

// ---------------- release/acquire helpers ----------------
__device__ __forceinline__ void st_release_gpu(unsigned* p, unsigned v) {
    asm volatile("st.release.gpu.global.u32 [%0], %1;" :: "l"(p), "r"(v) : "memory");
}
__device__ __forceinline__ unsigned ld_acquire_gpu(const unsigned* p) {
    unsigned v;
    asm volatile("ld.acquire.gpu.global.u32 %0, [%1];" : "=r"(v) : "l"(p) : "memory");
    return v;
}

// ---------------------------------------------------------------------------
// W transpose: g_WT[k][r] = W[r][k]
// ---------------------------------------------------------------------------
__global__ void transp_kernel(const float* __restrict__ W) {
    __shared__ float tile[32][33];
    int rx = blockIdx.x * 32, ry = blockIdx.y * 32;
    tile[threadIdx.y][threadIdx.x] = W[(ry + threadIdx.y) * HH + rx + threadIdx.x];
    __syncthreads();
    g_WT[(rx + threadIdx.y) * HH + ry + threadIdx.x] = tile[threadIdx.x][threadIdx.y];
}

// ---------------------------------------------------------------------------
// 512x512 matmul: stage 0: g_W2 = W*W ; stage 1: g_W4 = g_W2*g_W2.
// Block = 8 output rows, thread = one output column.
// ---------------------------------------------------------------------------
__global__ void __launch_bounds__(512, 1) mm_kernel(const float* __restrict__ W,
                                                    int stage) {
    const float* A = (stage == 0) ? W : g_W2;
    const float* B = A;
    float* C = (stage == 0) ? g_W2 : g_W4;

    __shared__ float as[8][HH];
    const int r0 = blockIdx.x * 8;
    for (int f = threadIdx.x; f < 8 * HH; f += 512)
        as[f >> 9][f & 511] = A[r0 * HH + f];
    __syncthreads();
    const int c = threadIdx.x;
    float acc[8];
#pragma unroll
    for (int r = 0; r < 8; r++) acc[r] = 0.0f;
#pragma unroll 4
    for (int k = 0; k < HH; k++) {
        const float bv = B[k * HH + c];
#pragma unroll
        for (int r = 0; r < 8; r++) acc[r] += as[r][k] * bv;
    }
#pragma unroll
    for (int r = 0; r < 8; r++) C[(r0 + r) * HH + c] = acc[r];
}

// ---------------------------------------------------------------------------
// Projection-weight chain: stage s computes Wp_s = W * Wp_{s-1} (Wp_0 = W_ih),
// b_s = W * b_{s-1}. Block = one output row, 96 threads.
// ---------------------------------------------------------------------------
__global__ void projw_kernel(const float* __restrict__ W,
                             const float* __restrict__ W_ih,
                             const float* __restrict__ b_ih,
                             int stage) {
    const float* src = (stage == 1) ? W_ih : (stage == 2) ? g_Wp1 : g_Wp2;
    const float* sb  = (stage == 1) ? b_ih : (stage == 2) ? g_b1  : g_b2;
    float* dst = (stage == 1) ? g_Wp1 : (stage == 2) ? g_Wp2 : g_Wp3;
    float* db  = (stage == 1) ? g_b1  : (stage == 2) ? g_b2  : g_b3;

    __shared__ float ar[HH];
    const int r = blockIdx.x;
    for (int f = threadIdx.x; f < HH; f += 96) ar[f] = W[r * HH + f];
    __syncthreads();
    const int i = threadIdx.x;
    if (i < II) {
        float a0 = 0.f, a1 = 0.f, a2 = 0.f, a3 = 0.f;
#pragma unroll 2
        for (int k = 0; k < HH; k += 4) {
            a0 += ar[k + 0] * src[(k + 0) * II + i];
            a1 += ar[k + 1] * src[(k + 1) * II + i];
            a2 += ar[k + 2] * src[(k + 2) * II + i];
            a3 += ar[k + 3] * src[(k + 3) * II + i];
        }
        dst[r * II + i] = (a0 + a1) + (a2 + a3);
    } else if (i == II) {
        float acc = 0.0f;
#pragma unroll 4
        for (int k = 0; k < HH; k++) acc += ar[k] * sb[k];
        db[r] = acc;
    }
}

// ---------------------------------------------------------------------------
// proj4: p0..p3 for all (t,n,h). Block stages 64 x-rows once, 4 weight sweeps.
// 4-way accumulator ILP inside each 88-dot.
// ---------------------------------------------------------------------------
__device__ __forceinline__ void proj_sweep(
    const float* __restrict__ wsrc, const float* __restrict__ bsrc,
    float* __restrict__ dst, const float (*xs)[II],
    int h, int n, int t0)
{
    float w[II];
#pragma unroll
    for (int i = 0; i < II; i++) w[i] = wsrc[h * II + i];
    const float b = bsrc[h];
#pragma unroll 1
    for (int j = 0; j < 64; j++) {
        float s0 = 0.f, s1 = 0.f, s2 = 0.f, s3 = 0.f;
        const float4* xr = reinterpret_cast<const float4*>(&xs[j][0]);
#pragma unroll
        for (int i4 = 0; i4 < II / 4; i4++) {
            float4 xv = xr[i4];
            s0 += w[4 * i4 + 0] * xv.x;
            s1 += w[4 * i4 + 1] * xv.y;
            s2 += w[4 * i4 + 2] * xv.z;
            s3 += w[4 * i4 + 3] * xv.w;
        }
        dst[((size_t)(t0 + j) * NB + n) * HH + h] = ((s0 + s1) + (s2 + s3)) + b;
    }
}

__global__ void __launch_bounds__(512, 1) proj4_kernel(
    const float* __restrict__ x,
    const float* __restrict__ W_ih,
    const float* __restrict__ b_ih)
{
    __shared__ __align__(16) float xs[64][II];
    const int h   = threadIdx.x;
    const int rr0 = blockIdx.x * 64;          // 64 | 2048 -> one n per block

    for (int f = threadIdx.x; f < 64 * II; f += 512)
        xs[f / II][f % II] = x[(size_t)rr0 * II + f];
    __syncthreads();

    const int n  = rr0 >> 11;
    const int t0 = rr0 & 2047;

    proj_sweep(W_ih,  b_ih, g_p0, xs, h, n, t0);
    proj_sweep(g_Wp1, g_b1, g_p1, xs, h, n, t0);
    proj_sweep(g_Wp2, g_b2, g_p2, xs, h, n, t0);
    proj_sweep(g_Wp3, g_b3, g_p3, xs, h, n, t0);
}

// ---------------------------------------------------------------------------
// h0 = initial + p0[0]; resets step flags.
// ---------------------------------------------------------------------------
__global__ void h0_kernel(const float* __restrict__ initial,
                          float* __restrict__ out, int dup)
{
    const int n = blockIdx.x, h = threadIdx.x;
    float v = initial[n * HH + h] + g_p0[(size_t)n * HH + h];
    out[(size_t)n * TH + h] = v;
    if (dup) out[NTOT + (size_t)n * TH + h] = v;
    if (blockIdx.x == 0 && threadIdx.x < NCTA) g_flag[threadIdx.x * 32] = 0u;
}

// ---------------------------------------------------------------------------
// Prologue: h_t = W h_{t-1} + p0[t-1] for t = 1,2,3. One block per batch.
// ---------------------------------------------------------------------------
__global__ void __launch_bounds__(512, 1) prologue_kernel(
    float* __restrict__ out, int dup)
{
    __shared__ float hs[HH];
    const int n = blockIdx.x, r = threadIdx.x;
    float h = out[(size_t)n * TH + r];        // h_0
#pragma unroll 1
    for (int t = 1; t <= 3; t++) {
        __syncthreads();
        hs[r] = h;
        __syncthreads();
        float a0 = 0.f, a1 = 0.f, a2 = 0.f, a3 = 0.f;
#pragma unroll 4
        for (int k = 0; k < HH; k += 4) {
            a0 += g_WT[(k + 0) * HH + r] * hs[k + 0];
            a1 += g_WT[(k + 1) * HH + r] * hs[k + 1];
            a2 += g_WT[(k + 2) * HH + r] * hs[k + 2];
            a3 += g_WT[(k + 3) * HH + r] * hs[k + 3];
        }
        h = (a0 + a1) + (a2 + a3)
          + g_p0[((size_t)(t - 1) * NB + n) * HH + r];
        out[(size_t)n * TH + (size_t)t * HH + r] = h;
        if (dup) out[NTOT + (size_t)n * TH + (size_t)t * HH + r] = h;
    }
}

// ---------------------------------------------------------------------------
// Warp butterfly over 64 partials: after 5 rounds lane L owns indices 2L, 2L+1.
// ---------------------------------------------------------------------------
template <int OFF, int M>
__device__ __forceinline__ void red_round(float* acc, int lane)
{
    const bool up = (lane & OFF) != 0;
#pragma unroll
    for (int i = 0; i < M; i++) {
        float keep = up ? acc[i + M] : acc[i];
        float send = up ? acc[i]     : acc[i + M];
        float recv = __shfl_xor_sync(0xffffffffu, send, OFF);
        acc[i] = keep + recv;
    }
}

// ---------------------------------------------------------------------------
// Persistent recurrence, D=4: h_t = W4 h_{t-4} + p3[t-4]+p2[t-3]+p1[t-2]+p0[t-1].
// 128 CTAs = 8 groups x 16. Group = 16 streams (4 batches x 4 chains).
// CTA = 32 rows x 16 streams; warp = 4 rows x 16 streams x full k.
// 511 barrier steps, flag-array release/acquire barrier.
// ---------------------------------------------------------------------------
__global__ void __launch_bounds__(256, 1) rnn_kernel(
    float* __restrict__ out, int dup)
{
    __shared__ __align__(16) float h_s[16 * HH];  // 32 KB: 16 streams' h_{t-4}

    const int tid  = threadIdx.x;
    const int wid  = tid >> 5;
    const int lane = tid & 31;
    const int bg   = blockIdx.x >> 4;    // group 0..7
    const int rg   = blockIdx.x & 15;    // CTA within group
    const int n0   = bg * 4;

    // Register W4 slice: warp owns 4 rows, lane owns k = lane + 32j
    const int rowbase = rg * 32 + wid * 4;
    float w[4][16];
#pragma unroll
    for (int r = 0; r < 4; r++)
#pragma unroll
        for (int j = 0; j < 16; j++)
            w[r][j] = g_W4[(rowbase + r) * HH + lane + 32 * j];

    // Outputs after butterfly: lane owns stream indices s0 = 2*lane&15, s0+1
    const int myRow = rowbase + (lane >> 3);
    const int s0    = (2 * lane) & 15;
    const int myN   = n0 + (s0 >> 2);
    const int c0    = s0 & 3;            // even chain; second output = c0+1

    // Staging map: 16 threads per stream, 8 float4 each
    const int ss = tid >> 4;             // stream 0..15
    const int si = tid & 15;
    const int sN = n0 + (ss >> 2);
    const int sc = ss & 3;

    unsigned* myFlag = &g_flag[(bg * GCTA + rg) * 32];
    const unsigned* pollFlag = &g_flag[(bg * GCTA + (tid & 15)) * 32];

    for (int k = 1; k <= KSTEPS; k++) {
        // ---- stage h_{t-4} for my stream slice
        {
            const int tprev = sc + 4 * (k - 1);
            const float4* src = reinterpret_cast<const float4*>(
                out + (size_t)sN * TH + (size_t)tprev * HH);
            float4* dst = reinterpret_cast<float4*>(&h_s[ss * HH]);
#pragma unroll
            for (int m = 0; m < 8; m++)
                dst[si + m * 16] = __ldcg(src + si + m * 16);
        }
        // ---- prefetch u for both outputs (independent of h)
        const int t0o = c0 + 4 * k;
        const size_t pb = (size_t)myN * HH + myRow;
        const size_t TS = (size_t)NB * HH;
        float uv0 = __ldg(&g_p0[(size_t)(t0o - 1) * TS + pb])
                  + __ldg(&g_p1[(size_t)(t0o - 2) * TS + pb])
                  + __ldg(&g_p2[(size_t)(t0o - 3) * TS + pb])
                  + __ldg(&g_p3[(size_t)(t0o - 4) * TS + pb]);
        float uv1 = __ldg(&g_p0[(size_t)(t0o + 0) * TS + pb])
                  + __ldg(&g_p1[(size_t)(t0o - 1) * TS + pb])
                  + __ldg(&g_p2[(size_t)(t0o - 2) * TS + pb])
                  + __ldg(&g_p3[(size_t)(t0o - 3) * TS + pb]);
        __syncthreads();

        // ---- 1024 FMA per thread: 4 rows x 16 streams x 16 k-values
        float acc[64];
#pragma unroll
        for (int i = 0; i < 64; i++) acc[i] = 0.0f;
#pragma unroll
        for (int j = 0; j < 16; j++) {
            const int kq = lane + 32 * j;
            float hv[16];
#pragma unroll
            for (int s = 0; s < 16; s++) hv[s] = h_s[s * HH + kq];
#pragma unroll
            for (int r = 0; r < 4; r++)
#pragma unroll
                for (int s = 0; s < 16; s++)
                    acc[r * 16 + s] += w[r][j] * hv[s];
        }

        // ---- butterfly 64 -> 2 per lane (indices 2*lane, 2*lane+1)
        red_round<16, 32>(acc, lane);
        red_round< 8, 16>(acc, lane);
        red_round< 4,  8>(acc, lane);
        red_round< 2,  4>(acc, lane);
        red_round< 1,  2>(acc, lane);

        const float v0 = acc[0] + uv0;
        const float v1 = acc[1] + uv1;
        const size_t oi0 = (size_t)myN * TH + (size_t)t0o * HH + myRow;
        const size_t oi1 = oi0 + HH;        // chain c0+1 at t0o+1
        out[oi0] = v0;
        out[oi1] = v1;
        if (dup) { out[NTOT + oi0] = v0; out[NTOT + oi1] = v1; }
        __syncthreads();                    // all CTA stores issued

        // ---- group barrier: per-CTA release flag, 16 parallel acquire polls
        if (tid == 0) st_release_gpu(myFlag, (unsigned)k);
        if (tid < GCTA) {
            while (ld_acquire_gpu(pollFlag) < (unsigned)k) { }
        }
        __syncthreads();
    }
}

// ---------------------------------------------------------------------------
// Launch: inputs in metadata order: x, initial, W_ih, b_ih, W_hh
// ---------------------------------------------------------------------------
extern "C" void kernel_launch(void* const* d_in, const int* in_sizes, int n_in,
                              void* d_out, int out_size)
{
    const float* x       = (const float*)d_in[0];
    const float* initial = (const float*)d_in[1];
    const float* W_ih    = (const float*)d_in[2];
    const float* b_ih    = (const float*)d_in[3];
    const float* W_hh    = (const float*)d_in[4];
    float* out = (float*)d_out;
    const int dup = (out_size >= 2 * NTOT) ? 1 : 0;

    dim3 tb(32, 32);
    dim3 tg(16, 16);
    transp_kernel<<<tg, tb>>>(W_hh);
    mm_kernel<<<HH / 8, 512>>>(W_hh, 0);      // W2
    mm_kernel<<<HH / 8, 512>>>(W_hh, 1);      // W4
    projw_kernel<<<HH, 96>>>(W_hh, W_ih, b_ih, 1);
    projw_kernel<<<HH, 96>>>(W_hh, W_ih, b_ih, 2);
    projw_kernel<<<HH, 96>>>(W_hh, W_ih, b_ih, 3);
    proj4_kernel<<<NROWS / 64, 512>>>(x, W_ih, b_ih);
    h0_kernel<<<NB, HH>>>(initial, out, dup);
    prologue_kernel<<<NB, HH>>>(out, dup);
    rnn_kernel<<<NCTA, 256>>>(out, dup);
}